// round 9
// baseline (speedup 1.0000x reference)
#include <cuda_runtime.h>
#include <cuda_fp16.h>
#include <cstdint>

// ============================================================================
// MQA_22436909154690 on GB300 (sm_103 base PTX target -> HMMA mma.sync path).
//
// Math: softmax over singleton axis == 1, so
//   out[b,l] = tile(v[b,l], H),  v = x @ Wv^T + bv,  Wv = Wkv[HD:2HD, :]
// => one GEMM [16384 x 2048] @ [2048 x 128] + bias + broadcast-x16 epilogue.
//
// R9: MTILE 64 -> 32, grid 512 (TWO waves at 2-3 CTAs/SM). R2-R8 ran as a
// single wave: read-only mainloop then write-only epilogue tail -> DRAM never
// sees reads+writes together (pinned ~44%). Two waves overlap wave-1 writes
// with wave-2 reads. Loop structure = R4 (A double-buffered via regs,
// B triple-buffered cp.async distance 2, one barrier/iter).
// ============================================================================

static constexpr int KDIM  = 2048;
static constexpr int MTILE = 32;
static constexpr int KC    = 64;
static constexpr int NCH   = KDIM / KC;       // 32 chunks

// SMEM (bytes); rows padded to 72 halves (144 B) for conflict-free ldmatrix.
static constexpr int SA0  = 0;                        // A buf0: [32][72] half
static constexpr int SA1  = 4608;                     // A buf1
static constexpr int SB   = 9216;                     // B: 3 x [128][72] half
static constexpr int SBSZ = 18432;
static constexpr int SMEM_TOTAL = SB + 3 * SBSZ;      // 64512 (x3 CTAs = 189 KB/SM)
static constexpr int V_STRIDE = 132;                  // epilogue overlay: 32x132x4

// Pre-converted Wv fp16, chunk-major: [chunk32][n=128][k=64]
__device__ __align__(16) __half g_Wh[KDIM * 128];

// ---------------------------------------------------------------------------
__device__ __forceinline__ uint32_t smem_u32(const void* p) {
    uint32_t a;
    asm("{ .reg .u64 t; cvta.to.shared.u64 t, %1; cvt.u32.u64 %0, t; }" : "=r"(a) : "l"(p));
    return a;
}
__device__ __forceinline__ void ldsm4(uint32_t* r, uint32_t addr) {
    asm volatile("ldmatrix.sync.aligned.m8n8.x4.shared.b16 {%0,%1,%2,%3}, [%4];"
                 : "=r"(r[0]), "=r"(r[1]), "=r"(r[2]), "=r"(r[3]) : "r"(addr));
}
__device__ __forceinline__ void hmma(float* d, const uint32_t* a, uint32_t b0, uint32_t b1) {
    asm volatile("mma.sync.aligned.m16n8k16.row.col.f32.f16.f16.f32 "
                 "{%0,%1,%2,%3}, {%4,%5,%6,%7}, {%8,%9}, {%0,%1,%2,%3};"
                 : "+f"(d[0]), "+f"(d[1]), "+f"(d[2]), "+f"(d[3])
                 : "r"(a[0]), "r"(a[1]), "r"(a[2]), "r"(a[3]), "r"(b0), "r"(b1));
}
template <int N>
__device__ __forceinline__ void cpwait() {
    asm volatile("cp.async.wait_group %0;" :: "n"(N) : "memory");
}
__device__ __forceinline__ void cpcommit() {
    asm volatile("cp.async.commit_group;" ::: "memory");
}
__device__ __forceinline__ void cpa16(uint32_t dst, const void* src) {
    asm volatile("cp.async.cg.shared.global [%0], [%1], 16;" :: "r"(dst), "l"(src) : "memory");
}
__device__ __forceinline__ uint32_t h2u(__half2 h) { return *reinterpret_cast<uint32_t*>(&h); }

// ---------------------------------------------------------------------------
// Pre-kernel: Wv = Wkv rows 128..255 -> fp16, chunk-major [c][n][k64].
// ---------------------------------------------------------------------------
__global__ void convert_w_kernel(const float* __restrict__ Wkv) {
    int idx = blockIdx.x * blockDim.x + threadIdx.x;  // 65536 units of 4 halves
    int h4 = idx << 2;
    int c  = h4 >> 13;
    int n  = (h4 >> 6) & 127;
    int k4 = h4 & 63;
    float4 w = *(const float4*)(Wkv + (size_t)(128 + n) * KDIM + c * KC + k4);
    __half2 p0 = __float22half2_rn(make_float2(w.x, w.y));
    __half2 p1 = __float22half2_rn(make_float2(w.z, w.w));
    *(uint2*)(g_Wh + h4) = make_uint2(h2u(p0), h2u(p1));
}

// ---------------------------------------------------------------------------
// 512 CTAs x 256 threads (2 waves). 8 warps as 2(M) x 4(N): 16x32 frags.
// ---------------------------------------------------------------------------
__global__ void __launch_bounds__(256, 3)
mqa_gemm_kernel(const float* __restrict__ x, const float* __restrict__ bkv,
                float* __restrict__ out) {
    extern __shared__ char smem[];
    const uint32_t sb = smem_u32(smem);
    const int tid    = threadIdx.x;
    const int wid    = tid >> 5;
    const int lane   = tid & 31;
    const int warp_m = wid >> 2;   // 0..1 (16 rows each)
    const int warp_n = wid & 3;    // 0..3 (32 cols each)

    const float* xb = x + (size_t)blockIdx.x * MTILE * KDIM;

    // ldmatrix offsets within A / B buffers
    const uint32_t aOff = (uint32_t)(warp_m * 16 + (lane & 15)) * 144 + ((lane >> 4) << 4);
    uint32_t bOff[2];
    #pragma unroll
    for (int g = 0; g < 2; ++g)
        bOff[g] = (uint32_t)(warp_n * 32 + g * 16 + (lane & 15)) * 144 + ((lane >> 4) << 4);

    float acc[4][4];
    #pragma unroll
    for (int nf = 0; nf < 4; ++nf)
        #pragma unroll
        for (int r = 0; r < 4; ++r) acc[nf][r] = 0.f;

    float4 xs[2];                  // staged x chunk: 32x64 fp32 / 256 thr = 2 float4

    auto ldx = [&](int ch) {
        #pragma unroll
        for (int i = 0; i < 2; ++i) {
            int u = tid + i * 256;                    // float4 unit, 0..511
            xs[i] = *(const float4*)(xb + (size_t)(u >> 4) * KDIM + ch * KC + ((u & 15) << 2));
        }
    };
    auto stx = [&](int buf) {
        uint32_t base = (buf ? SA1 : SA0);
        #pragma unroll
        for (int i = 0; i < 2; ++i) {
            int u = tid + i * 256;
            uint32_t lo = h2u(__float22half2_rn(make_float2(xs[i].x, xs[i].y)));
            uint32_t hi = h2u(__float22half2_rn(make_float2(xs[i].z, xs[i].w)));
            asm volatile("st.shared.v2.u32 [%0], {%1,%2};"
                         :: "r"(sb + base + (u >> 4) * 144 + ((u & 15) << 3)),
                            "r"(lo), "r"(hi) : "memory");
        }
    };
    auto cpB = [&](int ch, int buf) {
        const __half* src = g_Wh + (size_t)ch * (128 * KC);
        uint32_t dbase = sb + SB + buf * SBSZ;
        #pragma unroll
        for (int j = 0; j < 4; ++j) {
            int u = tid + j * 256;                    // 16B unit: n = u>>3, seg = u&7
            cpa16(dbase + (u >> 3) * 144 + ((u & 7) << 4),
                  src + (u >> 3) * KC + ((u & 7) << 3));
        }
        cpcommit();
    };
    auto mmaChunk = [&](int abuf, int bbuf) {
        uint32_t bA = sb + (abuf ? SA1 : SA0);
        uint32_t bB = sb + SB + bbuf * SBSZ;
        #pragma unroll
        for (int kk = 0; kk < 4; ++kk) {
            uint32_t a[4];
            ldsm4(a, bA + aOff + kk * 32);
            uint32_t b[2][4];
            ldsm4(b[0], bB + bOff[0] + kk * 32);
            ldsm4(b[1], bB + bOff[1] + kk * 32);
            hmma(acc[0], a, b[0][0], b[0][2]);
            hmma(acc[1], a, b[0][1], b[0][3]);
            hmma(acc[2], a, b[1][0], b[1][2]);
            hmma(acc[3], a, b[1][1], b[1][3]);
        }
    };

    // --- prologue: B chunks 0,1 in flight; A0 stored; chunk 1 staged ---
    cpB(0, 0);
    cpB(1, 1);
    ldx(0);
    stx(0);                 // one-time exposed LDG latency
    ldx(1);
    cpwait<1>();            // B chunk 0 resident
    __syncthreads();

    // --- main loop: ONE barrier per chunk (R4 structure) ---
    for (int it = 0; it < NCH; ++it) {
        // entering: A[it&1] + B[it%3] ready; xs holds chunk it+1 (in flight)
        if (it + 1 < NCH) stx((it + 1) & 1);        // LDGs had a full iter to land
        if (it + 2 < NCH) { ldx(it + 2); cpB(it + 2, (it + 2) % 3); }
        mmaChunk(it & 1, it % 3);
        if (it + 2 < NCH) cpwait<1>();              // B[it+1] done
        else              cpwait<0>();
        __syncthreads();                            // publishes A[(it+1)&1], B[it+1]
    }

    // --- epilogue ---
    float bias[4][2];
    {
        int c0 = warp_n * 32 + (lane & 3) * 2;
        #pragma unroll
        for (int nf = 0; nf < 4; ++nf) {
            bias[nf][0] = bkv[128 + c0 + nf * 8];
            bias[nf][1] = bkv[129 + c0 + nf * 8];
        }
    }
    __syncthreads();

    float* vsm = (float*)smem;
    {
        int r0 = warp_m * 16 + (lane >> 2);
        #pragma unroll
        for (int nf = 0; nf < 4; ++nf) {
            int c = warp_n * 32 + nf * 8 + (lane & 3) * 2;
            vsm[r0 * V_STRIDE + c]           = acc[nf][0] + bias[nf][0];
            vsm[r0 * V_STRIDE + c + 1]       = acc[nf][1] + bias[nf][1];
            vsm[(r0 + 8) * V_STRIDE + c]     = acc[nf][2] + bias[nf][0];
            vsm[(r0 + 8) * V_STRIDE + c + 1] = acc[nf][3] + bias[nf][1];
        }
    }
    __syncthreads();

    // Broadcast: each v row written 16x (one per head), fully coalesced.
    float* ob = out + (size_t)blockIdx.x * MTILE * 2048;
    for (int r = wid; r < MTILE; r += 8) {
        float4 val = *(const float4*)(vsm + r * V_STRIDE + lane * 4);
        float4* orow = (float4*)(ob + (size_t)r * 2048);
        #pragma unroll
        for (int h = 0; h < 16; ++h) orow[lane + h * 32] = val;
    }
}

// ---------------------------------------------------------------------------
extern "C" void kernel_launch(void* const* d_in, const int* in_sizes, int n_in,
                              void* d_out, int out_size) {
    const float* x   = (const float*)d_in[0];   // (4,4096,2048) fp32
    const float* Wkv = (const float*)d_in[3];   // (256,2048) fp32
    const float* bkv = (const float*)d_in[4];   // (256,) fp32
    float* out = (float*)d_out;                 // (4,4096,2048) fp32

    cudaFuncSetAttribute(mqa_gemm_kernel,
                         cudaFuncAttributeMaxDynamicSharedMemorySize, SMEM_TOTAL);

    convert_w_kernel<<<256, 256>>>(Wkv);
    mqa_gemm_kernel<<<16384 / MTILE, 256, SMEM_TOTAL>>>(x, bkv, out);
}

// round 10
// speedup vs baseline: 1.3285x; 1.3285x over previous
#include <cuda_runtime.h>
#include <cuda_fp16.h>
#include <cstdint>

// ============================================================================
// MQA_22436909154690 on GB300 (sm_103 base PTX target -> HMMA mma.sync path).
//
// Math: softmax over singleton axis == 1, so
//   out[b,l] = tile(v[b,l], H),  v = x @ Wv^T + bv,  Wv = Wkv[HD:2HD, :]
// => one GEMM [16384 x 2048] @ [2048 x 128] + bias + broadcast-x16 epilogue.
//
// R10 = R4 (best: 64.0us) + three surgical tweaks:
//  - __ldcs on x (read-once) and __stcs on out (write-once): evict-first,
//    stop 268MB of streaming traffic from churning L2.
//  - K-loop rotation by CTA parity: odd CTAs start at chunk 16 -> the two
//    co-resident CTAs' x/B bursts hit different addresses/phases.
//  - bias preloaded to regs before the mainloop.
// ============================================================================

static constexpr int KDIM  = 2048;
static constexpr int MTILE = 64;
static constexpr int KC    = 64;
static constexpr int NCH   = KDIM / KC;       // 32 chunks

// SMEM (bytes). 72 halves/row padding -> conflict-free ldmatrix.
static constexpr int SA0 = 0;                        // A buf0: [64][72] half
static constexpr int SA1 = 9216;                     // A buf1
static constexpr int SB  = 18432;                    // B bufs: 3 x [128][72] half
static constexpr int SBSZ = 18432;
static constexpr int SMEM_TOTAL = SB + 3 * SBSZ;     // 73728 (x2 CTAs/SM)
static constexpr int V_STRIDE  = 132;                // epilogue overlay (33792 B)

// Pre-converted Wv in fp16, chunk-major: [chunk][n=128][k=64]
__device__ __align__(16) __half g_Wh[KDIM * 128];

// ---------------------------------------------------------------------------
__device__ __forceinline__ uint32_t smem_u32(const void* p) {
    uint32_t a;
    asm("{ .reg .u64 t; cvta.to.shared.u64 t, %1; cvt.u32.u64 %0, t; }" : "=r"(a) : "l"(p));
    return a;
}
__device__ __forceinline__ void ldsm4(uint32_t* r, uint32_t addr) {
    asm volatile("ldmatrix.sync.aligned.m8n8.x4.shared.b16 {%0,%1,%2,%3}, [%4];"
                 : "=r"(r[0]), "=r"(r[1]), "=r"(r[2]), "=r"(r[3]) : "r"(addr));
}
__device__ __forceinline__ void hmma(float* d, const uint32_t* a, uint32_t b0, uint32_t b1) {
    asm volatile("mma.sync.aligned.m16n8k16.row.col.f32.f16.f16.f32 "
                 "{%0,%1,%2,%3}, {%4,%5,%6,%7}, {%8,%9}, {%0,%1,%2,%3};"
                 : "+f"(d[0]), "+f"(d[1]), "+f"(d[2]), "+f"(d[3])
                 : "r"(a[0]), "r"(a[1]), "r"(a[2]), "r"(a[3]), "r"(b0), "r"(b1));
}
template <int N>
__device__ __forceinline__ void cpwait() {
    asm volatile("cp.async.wait_group %0;" :: "n"(N) : "memory");
}
__device__ __forceinline__ void cpcommit() {
    asm volatile("cp.async.commit_group;" ::: "memory");
}
__device__ __forceinline__ void cpa16(uint32_t dst, const void* src) {
    asm volatile("cp.async.cg.shared.global [%0], [%1], 16;" :: "r"(dst), "l"(src) : "memory");
}
__device__ __forceinline__ uint32_t h2u(__half2 h) { return *reinterpret_cast<uint32_t*>(&h); }

// ---------------------------------------------------------------------------
// Pre-kernel: Wv = Wkv rows 128..255 -> fp16, chunk-major layout for cp.async.
// ---------------------------------------------------------------------------
__global__ void convert_w_kernel(const float* __restrict__ Wkv) {
    int idx = blockIdx.x * blockDim.x + threadIdx.x;  // 65536 units of 4 halves
    int h4 = idx << 2;
    int c  = h4 >> 13;            // chunk
    int n  = (h4 >> 6) & 127;     // output column
    int k4 = h4 & 63;             // k within chunk
    float4 w = *(const float4*)(Wkv + (size_t)(128 + n) * KDIM + c * KC + k4);
    __half2 p0 = __float22half2_rn(make_float2(w.x, w.y));
    __half2 p1 = __float22half2_rn(make_float2(w.z, w.w));
    *(uint2*)(g_Wh + h4) = make_uint2(h2u(p0), h2u(p1));
}

// ---------------------------------------------------------------------------
// 256 CTAs x 256 threads, 2 CTAs/SM. 8 warps as 2(M) x 4(N): 32x32 frags.
// ---------------------------------------------------------------------------
__global__ void __launch_bounds__(256, 2)
mqa_gemm_kernel(const float* __restrict__ x, const float* __restrict__ bkv,
                float* __restrict__ out) {
    extern __shared__ char smem[];
    const uint32_t sb = smem_u32(smem);
    const int tid    = threadIdx.x;
    const int wid    = tid >> 5;
    const int lane   = tid & 31;
    const int warp_m = wid >> 2;
    const int warp_n = wid & 3;
    const int skew   = (blockIdx.x & 1) * (NCH / 2);   // K rotation: decorrelate bursts

    const float* xb = x + (size_t)blockIdx.x * MTILE * KDIM;

    // Bias preload (before mainloop; bkv is tiny, L2-hot).
    float bias[4][2];
    {
        int c0 = warp_n * 32 + (lane & 3) * 2;
        #pragma unroll
        for (int nf = 0; nf < 4; ++nf) {
            bias[nf][0] = bkv[128 + c0 + nf * 8];
            bias[nf][1] = bkv[129 + c0 + nf * 8];
        }
    }

    // ldmatrix offsets (within an A / B buffer)
    uint32_t aOff[2];
    #pragma unroll
    for (int mf = 0; mf < 2; ++mf)
        aOff[mf] = (((warp_m * 32 + mf * 16 + (lane & 15)) * 72) << 1) + ((lane >> 4) << 4);
    uint32_t bOff[2];
    #pragma unroll
    for (int g = 0; g < 2; ++g)
        bOff[g] = (((warp_n * 32 + g * 16 + (lane & 15)) * 72) << 1) + ((lane >> 4) << 4);

    float acc[2][4][4];
    #pragma unroll
    for (int mf = 0; mf < 2; ++mf)
        #pragma unroll
        for (int nf = 0; nf < 4; ++nf)
            #pragma unroll
            for (int r = 0; r < 4; ++r) acc[mf][nf][r] = 0.f;

    float4 xs[2][2];                       // staged x chunk (next+1)
    const int f8a = tid;                   // 8-float unit indices for this thread
    const int f8b = tid + 256;

    auto ldx = [&](int ch) {
        const float* p0 = xb + (size_t)(f8a >> 3) * KDIM + ch * KC + ((f8a & 7) << 3);
        const float* p1 = xb + (size_t)(f8b >> 3) * KDIM + ch * KC + ((f8b & 7) << 3);
        xs[0][0] = __ldcs((const float4*)p0);
        xs[0][1] = __ldcs((const float4*)p0 + 1);
        xs[1][0] = __ldcs((const float4*)p1);
        xs[1][1] = __ldcs((const float4*)p1 + 1);
    };
    auto stx = [&](int buf) {
        uint32_t base = (buf ? SA1 : SA0);
        #pragma unroll
        for (int i = 0; i < 2; ++i) {
            int f8 = (i ? f8b : f8a);
            __half2 h0 = __float22half2_rn(make_float2(xs[i][0].x, xs[i][0].y));
            __half2 h1 = __float22half2_rn(make_float2(xs[i][0].z, xs[i][0].w));
            __half2 h2 = __float22half2_rn(make_float2(xs[i][1].x, xs[i][1].y));
            __half2 h3 = __float22half2_rn(make_float2(xs[i][1].z, xs[i][1].w));
            uint4 v = make_uint4(h2u(h0), h2u(h1), h2u(h2), h2u(h3));
            *(uint4*)(smem + base + (((f8 >> 3) * 72 + ((f8 & 7) << 3)) << 1)) = v;
        }
    };
    auto cpB = [&](int ch, int buf) {
        const __half* src = g_Wh + (size_t)ch * (128 * KC);
        uint32_t dbase = sb + SB + buf * SBSZ;
        #pragma unroll
        for (int j = 0; j < 4; ++j) {
            int idx = tid + j * 256;
            int n = idx >> 3, seg = idx & 7;
            cpa16(dbase + ((n * 72 + seg * 8) << 1), src + n * KC + seg * 8);
        }
        cpcommit();
    };
    auto mmaChunk = [&](int abuf, int bbuf) {
        uint32_t bA = sb + (abuf ? SA1 : SA0);
        uint32_t bB = sb + SB + bbuf * SBSZ;
        #pragma unroll
        for (int kk = 0; kk < 4; ++kk) {
            uint32_t a[2][4];
            ldsm4(a[0], bA + aOff[0] + kk * 32);
            ldsm4(a[1], bA + aOff[1] + kk * 32);
            uint32_t b[2][4];
            ldsm4(b[0], bB + bOff[0] + kk * 32);
            ldsm4(b[1], bB + bOff[1] + kk * 32);
            #pragma unroll
            for (int mf = 0; mf < 2; ++mf) {
                hmma(acc[mf][0], a[mf], b[0][0], b[0][2]);
                hmma(acc[mf][1], a[mf], b[0][1], b[0][3]);
                hmma(acc[mf][2], a[mf], b[1][0], b[1][2]);
                hmma(acc[mf][3], a[mf], b[1][1], b[1][3]);
            }
        }
    };

    // --- prologue: B chunks 0,1 in flight; A chunk 0 stored; chunk 1 staged ---
    cpB(skew, 0);
    cpB(skew + 1, 1);
    ldx(skew);
    stx(0);                 // one-time exposed LDG latency
    ldx(skew + 1);
    cpwait<1>();            // B chunk 0 resident
    __syncthreads();

    // --- main loop: ONE barrier per chunk; K order rotated by skew ---
    for (int it = 0; it < NCH; ++it) {
        if (it + 1 < NCH) stx((it + 1) & 1);        // LDGs had a full iter to land
        if (it + 2 < NCH) {
            ldx((it + 2 + skew) & 31);
            cpB((it + 2 + skew) & 31, (it + 2) % 3);
        }
        mmaChunk(it & 1, it % 3);
        if (it + 2 < NCH) cpwait<1>();              // B[it+1] done
        else              cpwait<0>();
        __syncthreads();                            // publishes A[(it+1)&1], B[it+1]
    }

    // --- epilogue ---
    __syncthreads();
    float* vsm = (float*)smem;
    {
        int r0 = warp_m * 32 + (lane >> 2);
        #pragma unroll
        for (int mf = 0; mf < 2; ++mf) {
            #pragma unroll
            for (int nf = 0; nf < 4; ++nf) {
                int r = r0 + mf * 16;
                int c = warp_n * 32 + nf * 8 + (lane & 3) * 2;
                vsm[r * V_STRIDE + c]           = acc[mf][nf][0] + bias[nf][0];
                vsm[r * V_STRIDE + c + 1]       = acc[mf][nf][1] + bias[nf][1];
                vsm[(r + 8) * V_STRIDE + c]     = acc[mf][nf][2] + bias[nf][0];
                vsm[(r + 8) * V_STRIDE + c + 1] = acc[mf][nf][3] + bias[nf][1];
            }
        }
    }
    __syncthreads();

    // Broadcast: each v row written 16x (one per head), coalesced, evict-first.
    float* ob = out + (size_t)blockIdx.x * MTILE * 2048;
    for (int r = wid; r < MTILE; r += 8) {
        float4 val = *(const float4*)(vsm + r * V_STRIDE + lane * 4);
        float4* orow = (float4*)(ob + (size_t)r * 2048);
        #pragma unroll
        for (int h = 0; h < 16; ++h) __stcs(orow + lane + h * 32, val);
    }
}

// ---------------------------------------------------------------------------
extern "C" void kernel_launch(void* const* d_in, const int* in_sizes, int n_in,
                              void* d_out, int out_size) {
    const float* x   = (const float*)d_in[0];   // (4,4096,2048) fp32
    const float* Wkv = (const float*)d_in[3];   // (256,2048) fp32
    const float* bkv = (const float*)d_in[4];   // (256,) fp32
    float* out = (float*)d_out;                 // (4,4096,2048) fp32

    cudaFuncSetAttribute(mqa_gemm_kernel,
                         cudaFuncAttributeMaxDynamicSharedMemorySize, SMEM_TOTAL);

    convert_w_kernel<<<256, 256>>>(Wkv);
    mqa_gemm_kernel<<<16384 / MTILE, 256, SMEM_TOTAL>>>(x, bkv, out);
}